// round 5
// baseline (speedup 1.0000x reference)
#include <cuda_runtime.h>
#include <math.h>
#include <stdint.h>

#define TWO_PI_F 6.28318530717958647692f
#define NT    12
#define KMIX  16
#define HDIM  256
#define BATCH 64
#define LLEN  3072
#define NLINK 1024
#define SAMP  64
#define NTHR  256
#define KC    32
#define EPSF  1e-6f

typedef unsigned long long ull;

// ---- scratch (static device memory; no allocations) ----
__device__ float g_z[BATCH * LLEN];
__device__ float g_ldj[BATCH * NLINK];

// smem layout (floats)
#define OFF_H1   0                        // 64*257 = 16448 (h1, reused as h2)
#define WB_HALF  (KC * HDIM)              // 8192 floats per W2 chunk buffer
#define OFF_WB   16448                    // 2*8192 = 16384 (W2 dbl-buf; W3 12288 reuses)
#define OFF_PRM  (OFF_WB + 2 * WB_HALF)   // 64*48 = 3072
#define OFF_C1   (OFF_PRM + 3072)         // 64
#define OFF_C2   (OFF_C1 + 64)
#define OFF_VI   (OFF_C2 + 64)
#define OFF_ZR   (OFF_VI + 64)
#define SMEM_FLOATS (OFF_ZR + 64)         // 36160 floats
#define SMEM_BYTES (SMEM_FLOATS * 4)      // 144640 B

__device__ __forceinline__ float mod2pi(float x) {
    float r = fmodf(x, TWO_PI_F);
    if (r < 0.0f) r += TWO_PI_F;
    return r;
}

__device__ __forceinline__ void cpasync16(uint32_t dst_smem, const void* src) {
    asm volatile("cp.async.cg.shared.global [%0], [%1], 16;\n"
                 :: "r"(dst_smem), "l"(src));
}
__device__ __forceinline__ void cpasync_commit() {
    asm volatile("cp.async.commit_group;\n" ::: "memory");
}
__device__ __forceinline__ void cpasync_wait0() {
    asm volatile("cp.async.wait_group 0;\n" ::: "memory");
}

__global__ void copy_in_kernel(const float* __restrict__ z) {
    int i = blockIdx.x * blockDim.x + threadIdx.x;
    if (i < BATCH * LLEN) g_z[i] = z[i];
}

__global__ __launch_bounds__(NTHR, 1)
void step_kernel(const float* __restrict__ W1, const float* __restrict__ b1,
                 const float* __restrict__ W2, const float* __restrict__ b2,
                 const float* __restrict__ W3, const float* __restrict__ b3,
                 int t) {
    extern __shared__ float smem[];
    float* h1   = smem + OFF_H1;    // [s*257 + h]
    float* wbuf = smem + OFF_WB;    // double buffer: halves of WB_HALF floats
    float* prm  = smem + OFF_PRM;   // [s*48 + o]
    float* c1s  = smem + OFF_C1;
    float* c2s  = smem + OFF_C2;
    float* vis  = smem + OFF_VI;
    float* zrs  = smem + OFF_ZR;

    const int tid = threadIdx.x;
    const int bx  = blockIdx.x;
    const int b   = bx >> 4;             // batch row 0..63
    const int j0  = (bx & 15) * SAMP;    // link block start
    const int tm3 = t % 3;
    const int off = (tm3 == 0) ? 0 : ((tm3 == 1) ? 2 : 1);

    const float* W2t = W2 + (size_t)t * HDIM * HDIM;

    // ---------- Prefetch W2 chunk 0 (overlaps phases A & B) ----------
    {
        uint32_t dst = (uint32_t)__cvta_generic_to_shared(wbuf) + tid * 16u;
        const char* src = (const char*)W2t + tid * 16u;
        #pragma unroll
        for (int i = 0; i < (WB_HALF * 4) / (NTHR * 16); i++)
            cpasync16(dst + i * NTHR * 16u, src + i * NTHR * 16u);
        cpasync_commit();
    }

    // ---------- Phase A: gather context from z ----------
    if (tid < SAMP) {
        int j = j0 + tid;
        int idx = 3 * j + off;
        const float* zrow = g_z + b * LLEN;
        int im2 = idx - 2; if (im2 < 0) im2 += LLEN;
        int im1 = idx - 1; if (im1 < 0) im1 += LLEN;
        int ip1 = idx + 1; if (ip1 >= LLEN) ip1 -= LLEN;
        int ip2 = idx + 2; if (ip2 >= LLEN) ip2 -= LLEN;
        float zm2 = zrow[im2], zm1 = zrow[im1], z0 = zrow[idx];
        float zp1 = zrow[ip1], zp2 = zrow[ip2];
        c1s[tid] = mod2pi(zm1 - zm2);
        c2s[tid] = mod2pi(zp2 - zp1);
        vis[tid] = mod2pi(z0 - zm1);
        zrs[tid] = zm1;
    }
    __syncthreads();

    // ---------- Layer 1: h1 = tanh(ctx @ W1 + b1), one h-unit per thread ----------
    {
        float w1a = W1[(t * 2 + 0) * HDIM + tid];
        float w1b = W1[(t * 2 + 1) * HDIM + tid];
        float bb1 = b1[t * HDIM + tid];
        #pragma unroll 4
        for (int s = 0; s < SAMP; s++) {
            h1[s * 257 + tid] = tanhf(c1s[s] * w1a + c2s[s] * w1b + bb1);
        }
    }
    __syncthreads();

    // ---------- Layer 2: h2 = tanh(h1 @ W2 + b2) ----------
    // thread (r = tid>>5, c = tid&31): samples r*8+m (m=0..7),
    // output pairs (2c+64n, 2c+64n+1), n=0..3. FFMA2 packed fp32.
    // W2 chunks double-buffered via cp.async; load of chunk ch+1 overlaps
    // compute of chunk ch.
    const int r = tid >> 5;
    const int c = tid & 31;

    ull acc[8][4];
    #pragma unroll
    for (int m = 0; m < 8; m++)
        #pragma unroll
        for (int n = 0; n < 4; n++) acc[m][n] = 0ull;

    for (int ch = 0; ch < HDIM / KC; ch++) {
        cpasync_wait0();        // chunk ch landed in wbuf[ch&1]
        __syncthreads();        // visible to all; all reads of wbuf[ch&1] from
                                // iteration ch-2 are also complete past here
        if (ch + 1 < HDIM / KC) {
            float* nxt = wbuf + ((ch + 1) & 1) * WB_HALF;
            uint32_t dst = (uint32_t)__cvta_generic_to_shared(nxt) + tid * 16u;
            const char* src = (const char*)(W2t + (ch + 1) * KC * HDIM) + tid * 16u;
            #pragma unroll
            for (int i = 0; i < (WB_HALF * 4) / (NTHR * 16); i++)
                cpasync16(dst + i * NTHR * 16u, src + i * NTHR * 16u);
            cpasync_commit();
        }

        const float* cur = wbuf + (ch & 1) * WB_HALF;
        #pragma unroll 4
        for (int kk = 0; kk < KC; kk++) {
            int kglob = ch * KC + kk;
            ull hd[8];
            #pragma unroll
            for (int m = 0; m < 8; m++) {
                float h = h1[(r * 8 + m) * 257 + kglob];  // warp broadcast
                asm("mov.b64 %0, {%1, %1};" : "=l"(hd[m]) : "r"(__float_as_uint(h)));
            }
            const float* wrow = cur + kk * HDIM;
            ull wv[4];
            #pragma unroll
            for (int n = 0; n < 4; n++)
                wv[n] = *(const ull*)(wrow + 2 * c + 64 * n);   // LDS.64, conflict-free
            #pragma unroll
            for (int m = 0; m < 8; m++)
                #pragma unroll
                for (int n = 0; n < 4; n++)
                    asm("fma.rn.f32x2 %0, %1, %2, %0;"
                        : "+l"(acc[m][n]) : "l"(hd[m]), "l"(wv[n]));
        }
    }
    __syncthreads();   // all compute done before wbuf is overwritten with W3

    // epilogue: h2 = tanh(acc + b2) written back into h1 buffer (all reads done)
    {
        float2 bb2[4];
        #pragma unroll
        for (int n = 0; n < 4; n++)
            bb2[n] = *(const float2*)(b2 + t * HDIM + 2 * c + 64 * n);
        #pragma unroll
        for (int m = 0; m < 8; m++) {
            int srow = (r * 8 + m) * 257;
            #pragma unroll
            for (int n = 0; n < 4; n++) {
                float2 a = *(float2*)&acc[m][n];
                int o = 2 * c + 64 * n;
                h1[srow + o]     = tanhf(a.x + bb2[n].x);
                h1[srow + o + 1] = tanhf(a.y + bb2[n].y);
            }
        }
    }

    // load W3[t] (256 x 48) into wbuf
    {
        const float4* src = (const float4*)(W3 + (size_t)t * HDIM * 48);
        float4* dst = (float4*)wbuf;
        #pragma unroll
        for (int i = 0; i < (HDIM * 48 / 4) / NTHR; i++)
            dst[tid + i * NTHR] = src[tid + i * NTHR];
    }
    __syncthreads();

    // ---------- Layer 3: params = h2 @ W3 + b3 ----------
    // thread (s = tid&63, grp = tid>>6): outputs grp*12 .. grp*12+11
    // f32x2 packed accumulators + LDS.128 weight loads.
    {
        const int s = tid & 63;
        const int grp = tid >> 6;
        ull acc3[6];
        {
            const float* bb = b3 + t * 48 + grp * 12;
            #pragma unroll
            for (int i = 0; i < 6; i++) {
                float2 v = *(const float2*)(bb + 2 * i);
                acc3[i] = *(const ull*)&v;
            }
        }
        #pragma unroll 4
        for (int k = 0; k < HDIM; k++) {
            float h = h1[s * 257 + k];                 // conflict-free (stride 257)
            ull hd;
            asm("mov.b64 %0, {%1, %1};" : "=l"(hd) : "r"(__float_as_uint(h)));
            const float4* wr = (const float4*)(wbuf + k * 48 + grp * 12); // 16B-aligned
            float4 w0 = wr[0], w1 = wr[1], w2 = wr[2]; // warp-broadcast LDS.128
            ull wv[6];
            wv[0] = *(ull*)&w0.x; wv[1] = *(ull*)&w0.z;
            wv[2] = *(ull*)&w1.x; wv[3] = *(ull*)&w1.z;
            wv[4] = *(ull*)&w2.x; wv[5] = *(ull*)&w2.z;
            #pragma unroll
            for (int i = 0; i < 6; i++)
                asm("fma.rn.f32x2 %0, %1, %2, %0;"
                    : "+l"(acc3[i]) : "l"(hd), "l"(wv[i]));
        }
        #pragma unroll
        for (int i = 0; i < 6; i++) {
            float2 v = *(float2*)&acc3[i];
            prm[s * 48 + grp * 12 + 2 * i]     = v.x;
            prm[s * 48 + grp * 12 + 2 * i + 1] = v.y;
        }
    }
    __syncthreads();

    // ---------- Phase D: mixture-CDF transform, per sample ----------
    if (tid < SAMP) {
        const float* p = prm + tid * 48;   // [0:16) log_scale, [16:32) shift, [32:48) wlogit

        // softmax over wlogits
        float mx = p[32];
        #pragma unroll
        for (int k = 1; k < KMIX; k++) mx = fmaxf(mx, p[32 + k]);
        float e[KMIX];
        float se = 0.0f;
        #pragma unroll
        for (int k = 0; k < KMIX; k++) { e[k] = expf(p[32 + k] - mx); se += e[k]; }
        float winv = 0.84f / se;           // (1 - K*MIN_W) = 0.84

        float u = vis[tid] * (1.0f / TWO_PI_F);
        u = fminf(fmaxf(u, EPSF), 1.0f - EPSF);
        float a  = u * u;
        float bq = (1.0f - u) * (1.0f - u);
        float apb = a + bq;
        float sv = a / apb;
        float ds_du = 2.0f * u * (1.0f - u) / (apb * apb);
        sv = fminf(fmaxf(sv, EPSF), 1.0f - EPSF);
        float logit_s = logf(sv) - log1pf(-sv);

        float y = 0.0f, dys = 0.0f;
        #pragma unroll
        for (int k = 0; k < KMIX; k++) {
            float al = expf(p[k]);
            float tt = al * (logit_s + p[16 + k]);
            float g = 1.0f / (1.0f + expf(-tt));
            float w = e[k] * winv + 0.01f;
            y   += w * g;
            dys += w * al * g * (1.0f - g);
        }
        float dy_du = dys / (sv * (1.0f - sv)) * ds_du;
        float lval = logf(dy_du);

        int gid = b * NLINK + j0 + tid;
        if (t == 0) g_ldj[gid] = lval;
        else        g_ldj[gid] += lval;

        int idx = 3 * (j0 + tid) + off;
        g_z[b * LLEN + idx] = mod2pi(TWO_PI_F * y + zrs[tid]);
    }
}

__global__ void finalize_kernel(float* __restrict__ out) {
    __shared__ float red[NTHR];
    int b = blockIdx.x;
    int tid = threadIdx.x;
    // copy z row
    for (int i = tid; i < LLEN; i += NTHR)
        out[b * LLEN + i] = g_z[b * LLEN + i];
    // deterministic ldj reduction (fixed order)
    float sum = 0.0f;
    for (int i = tid; i < NLINK; i += NTHR)
        sum += g_ldj[b * NLINK + i];
    red[tid] = sum;
    __syncthreads();
    for (int s = NTHR / 2; s > 0; s >>= 1) {
        if (tid < s) red[tid] += red[tid + s];
        __syncthreads();
    }
    if (tid == 0) out[BATCH * LLEN + b] = red[0];
}

extern "C" void kernel_launch(void* const* d_in, const int* in_sizes, int n_in,
                              void* d_out, int out_size) {
    const float* z  = (const float*)d_in[0];
    const float* W1 = (const float*)d_in[1];
    const float* b1 = (const float*)d_in[2];
    const float* W2 = (const float*)d_in[3];
    const float* b2 = (const float*)d_in[4];
    const float* W3 = (const float*)d_in[5];
    const float* b3 = (const float*)d_in[6];

    cudaFuncSetAttribute(step_kernel,
                         cudaFuncAttributeMaxDynamicSharedMemorySize, SMEM_BYTES);

    copy_in_kernel<<<(BATCH * LLEN + 255) / 256, 256>>>(z);
    for (int t = 0; t < NT; t++) {
        step_kernel<<<BATCH * (NLINK / SAMP), NTHR, SMEM_BYTES>>>(
            W1, b1, W2, b2, W3, b3, t);
    }
    finalize_kernel<<<BATCH, NTHR>>>((float*)d_out);
}